// round 16
// baseline (speedup 1.0000x reference)
#include <cuda_runtime.h>
#include <cstdint>

// ---------------- problem constants ----------------
#define C_CORES 64
#define D_EMB   128
#define CD      (C_CORES * D_EMB)      // 8192
#define TPB     1024                   // 32 warps: warp w owns cores 2w, 2w+1
#define CAP     96                     // per-core local bin capacity (mean ~21)
#define SR      6                      // rows per cp.async batch (3 KB)
#define BATB    (SR * D_EMB * 4)       // 3072 B per stage buffer
#define STAGE_BYTES (32 * 2 * BATB)    // 196608 B (32 warps x 2 buffers)

// ---------------- global scratch (zero state; kernel self-restores) ------
__device__ int          g_cnt[C_CORES];            // per-core counts
__device__ unsigned int g_tab[CD];                 // encoded segmax table
__device__ int gb2a, gb2d, gb3a, gb3d;             // barrier counters

__device__ __forceinline__ unsigned int enc(float f) {
    unsigned int u = __float_as_uint(f);
    return (u & 0x80000000u) ? ~u : (u | 0x80000000u);
}
__device__ __forceinline__ float dec(unsigned int u) {
    u = (u & 0x80000000u) ? (u & 0x7fffffffu) : ~u;
    return __uint_as_float(u);
}
__device__ __forceinline__ float neg_inf() { return __int_as_float(0xff800000); }

__device__ __forceinline__ uint32_t smem_u32(const void* p) {
    uint32_t a;
    asm("{ .reg .u64 t; cvta.to.shared.u64 t, %1; cvt.u32.u64 %0, t; }" : "=r"(a) : "l"(p));
    return a;
}
__device__ __forceinline__ void cpa16(uint32_t dst, const void* src) {
    asm volatile("cp.async.ca.shared.global [%0], [%1], 16;" :: "r"(dst), "l"(src));
}
__device__ __forceinline__ void cpa_commit() {
    asm volatile("cp.async.commit_group;" ::: "memory");
}

#define FMAX4(d, v) { d.x = fmaxf(d.x, (v).x); d.y = fmaxf(d.y, (v).y); \
                      d.z = fmaxf(d.z, (v).z); d.w = fmaxf(d.w, (v).w); }

__global__ __launch_bounds__(TPB, 1)
void fused(const int*   __restrict__ assign,
           const float* __restrict__ emb,
           const float* __restrict__ padding_emb,
           const float* __restrict__ core_con,
           const float* __restrict__ W_self,
           const float* __restrict__ W_msg,
           const float* __restrict__ bvec,
           float*       __restrict__ out,
           int Q)
{
    extern __shared__ char smraw[];
    const int tid  = threadIdx.x;
    const int wid  = tid >> 5;
    const int lane = tid & 31;
    const int grid = gridDim.x;

    const float4* e4 = (const float4*)emb;

    // smem layout (phase 1): [stages 192KB][s_cnt 256B][s_bin 24KB]
    int* s_cnt = (int*)(smraw + STAGE_BYTES);
    int* s_bin = s_cnt + C_CORES;

    // ============ phase 1a: bin this block's slice into smem lists ========
    {
        if (tid < C_CORES) s_cnt[tid] = 0;
        __syncthreads();

        const int chunk = (Q + grid - 1) / grid;
        const int qa0 = blockIdx.x * chunk;
        const int qa1 = min(qa0 + chunk, Q);

        for (int i = qa0 + tid; i < qa1; i += TPB) {
            int c = __ldg(assign + i);
            int idx = atomicAdd(&s_cnt[c], 1);
            if (idx < CAP) {
                s_bin[c * CAP + idx] = i;
            } else {
                // cold overflow path (prob ~0): fold the row directly
                const float4* row = e4 + (size_t)i * 32;
                for (int j = 0; j < 32; j++) {
                    float4 v = __ldg(row + j);
                    unsigned int* gp = g_tab + c * D_EMB + j * 4;
                    atomicMax(gp + 0, enc(v.x));
                    atomicMax(gp + 1, enc(v.y));
                    atomicMax(gp + 2, enc(v.z));
                    atomicMax(gp + 3, enc(v.w));
                }
            }
        }
        __syncthreads();

        if (tid < C_CORES && s_cnt[tid] > 0)
            atomicAdd(&g_cnt[tid], s_cnt[tid]);
    }

    // ===== phase 1b: cp.async depth-2 pipelined gather, 2 cores/warp ======
    {
        const int coreA = wid * 2;
        const int coreB = wid * 2 + 1;
        const int nA = min(s_cnt[coreA], CAP);
        const int nB = min(s_cnt[coreB], CAP);
        const int* listA = s_bin + coreA * CAP;
        const int* listB = s_bin + coreB * CAP;
        const int nbA = (nA + SR - 1) / SR;
        const int nbB = (nB + SR - 1) / SR;
        const int NB  = nbA + nbB;

        float* stage = (float*)(smraw + wid * 2 * BATB);   // 2 x 3KB buffers
        const uint32_t st_a = smem_u32(stage);

        float4 accA = make_float4(neg_inf(), neg_inf(), neg_inf(), neg_inf());
        float4 accB = accA;

        // issue batch k: 6 clamped rows -> stage buffer (k&1), one commit
        auto do_issue = [&](int k) {
            const int isB   = (k >= nbA);
            const int base  = (k - (isB ? nbA : 0)) * SR;
            const int* list = isB ? listB : listA;
            const int nlast = (isB ? nB : nA) - 1;
            int q32 = list[min(base + lane, nlast)];       // lanes 0..SR-1 used
            const uint32_t dst = st_a + (k & 1) * BATB + lane * 16;
#pragma unroll
            for (int j = 0; j < SR; j++) {
                int q = __shfl_sync(0xffffffffu, q32, j);
                cpa16(dst + j * 512, emb + (size_t)q * D_EMB + lane * 4);
            }
        };

        if (NB > 0) {
            do_issue(0);
            cpa_commit();
            for (int k = 0; k < NB; k++) {
                if (k + 1 < NB) do_issue(k + 1);
                cpa_commit();                              // exactly 1 group/iter
                asm volatile("cp.async.wait_group 1;" ::: "memory");
                __syncwarp();

                const float4* buf = (const float4*)(stage + (k & 1) * (BATB / 4));
                if (k < nbA) {
#pragma unroll
                    for (int j = 0; j < SR; j++) {
                        float4 v = buf[j * 32 + lane];
                        FMAX4(accA, v);                    // clamped dups: no-op
                    }
                } else {
#pragma unroll
                    for (int j = 0; j < SR; j++) {
                        float4 v = buf[j * 32 + lane];
                        FMAX4(accB, v);
                    }
                }
                __syncwarp();
            }
            asm volatile("cp.async.wait_group 0;" ::: "memory");
            __syncwarp();

            if (nA > 0) {
                unsigned int* gp = g_tab + coreA * D_EMB + lane * 4;
                atomicMax(gp + 0, enc(accA.x));
                atomicMax(gp + 1, enc(accA.y));
                atomicMax(gp + 2, enc(accA.z));
                atomicMax(gp + 3, enc(accA.w));
            }
            if (nB > 0) {
                unsigned int* gp = g_tab + coreB * D_EMB + lane * 4;
                atomicMax(gp + 0, enc(accB.x));
                atomicMax(gp + 1, enc(accB.y));
                atomicMax(gp + 2, enc(accB.z));
                atomicMax(gp + 3, enc(accB.w));
            }
        }
    }

    // ================= grid barrier (blocks >= 64 exit) ====================
    __threadfence();
    __syncthreads();
    if (blockIdx.x >= C_CORES) {
        if (tid == 0) atomicAdd(&gb2a, 1);
        return;
    }
    if (tid == 0) {
        atomicAdd(&gb2a, 1);
        while (atomicAdd(&gb2a, 0) < grid) __nanosleep(32);
        if (atomicAdd(&gb2d, 1) == C_CORES - 1) {
            atomicExch(&gb2a, 0);
            atomicExch(&gb2d, 0);
        }
        __threadfence();
    }
    __syncthreads();

    // ================= epilogue: decode E + fused GNN =====================
    float (*sE)[D_EMB] = (float(*)[D_EMB])smraw;          // 32 KB (reuse)
    float* sMp = (float*)smraw + CD;                      // 8 x 128
    float* sM  = sMp + 8 * D_EMB;                         // 128
    float* sO  = sM + D_EMB;                              // 8 x 128

    const int c = blockIdx.x;
    const int t = tid & 127;
    const int s = tid >> 7;                               // 0..7

    {
        const float pad = __ldg(&padding_emb[t]);
#pragma unroll
        for (int j = s * 8; j < s * 8 + 8; j++) {
            int cnt = __ldcg(&g_cnt[j]);
            unsigned int u = __ldcg(&g_tab[j * D_EMB + t]);
            sE[j][t] = (cnt > 0) ? dec(u) : pad;
        }
    }
    __syncthreads();

    // ---- barrier among the 64 epilogue blocks (all reads done) -----------
    if (tid == 0) {
        atomicAdd(&gb3a, 1);
        while (atomicAdd(&gb3a, 0) < C_CORES) __nanosleep(32);
        if (atomicAdd(&gb3d, 1) == C_CORES - 1) {
            atomicExch(&gb3a, 0);
            atomicExch(&gb3d, 0);
        }
        __threadfence();
    }
    __syncthreads();

    // restore zero state for next graph replay
    if (tid < 32) ((uint4*)g_tab)[c * 32 + tid] = make_uint4(0, 0, 0, 0);
    if (c == 0 && tid >= 32 && tid < 32 + C_CORES) g_cnt[tid - 32] = 0;

    // Msum[t] = sum_j con[c,j] * E[j,t]   (8-way split)
    {
        float a = 0.f;
#pragma unroll
        for (int j = s * 8; j < s * 8 + 8; j++)
            a = fmaf(__ldg(&core_con[c * C_CORES + j]), sE[j][t], a);
        sMp[s * D_EMB + t] = a;
    }
    __syncthreads();
    if (s == 0) {
        float m = 0.f;
#pragma unroll
        for (int r = 0; r < 8; r++) m += sMp[r * D_EMB + t];
        sM[t] = m;
    }
    __syncthreads();

    // out = relu(E@W_self + Msum@W_msg + b)   (8-way K split)
    {
        float a0 = 0.f, a1 = 0.f;
#pragma unroll
        for (int kk = s * 16; kk < s * 16 + 16; kk++) {
            a0 = fmaf(sE[c][kk], __ldg(&W_self[kk * D_EMB + t]), a0);
            a1 = fmaf(sM[kk],    __ldg(&W_msg [kk * D_EMB + t]), a1);
        }
        sO[s * D_EMB + t] = a0 + a1;
    }
    __syncthreads();
    if (s == 0) {
        float r = __ldg(&bvec[t]);
#pragma unroll
        for (int q = 0; q < 8; q++) r += sO[q * D_EMB + t];
        out[c * D_EMB + t] = fmaxf(r, 0.f);
    }
}

// ---------------- launch ----------------
extern "C" void kernel_launch(void* const* d_in, const int* in_sizes, int n_in,
                              void* d_out, int out_size)
{
    const int*   assign      = (const int*)  d_in[0];
    const float* emb         = (const float*)d_in[1];
    const float* padding_emb = (const float*)d_in[2];
    const float* core_con    = (const float*)d_in[3];
    const float* W_self      = (const float*)d_in[4];
    const float* W_msg       = (const float*)d_in[5];
    const float* bvec        = (const float*)d_in[6];
    float* out = (float*)d_out;

    const int Q = in_sizes[0];

    int nsm = 148;
    cudaDeviceGetAttribute(&nsm, cudaDevAttrMultiProcessorCount, 0);
    if (nsm < C_CORES) nsm = C_CORES;

    // smem: stages (192KB) + s_cnt (256B) + bins (24KB) = ~221.4 KB
    int smem = STAGE_BYTES + (C_CORES + C_CORES * CAP) * (int)sizeof(int);

    cudaFuncSetAttribute(fused, cudaFuncAttributeMaxDynamicSharedMemorySize, smem);
    fused<<<nsm, TPB, smem>>>(assign, emb, padding_emb, core_con,
                              W_self, W_msg, bvec, out, Q);
}

// round 17
// speedup vs baseline: 1.6684x; 1.6684x over previous
#include <cuda_runtime.h>
#include <cstdint>

// ---------------- problem constants ----------------
#define C_CORES 64
#define D_EMB   128
#define CD      (C_CORES * D_EMB)      // 8192
#define TPB     1024                   // 32 warps: warp w owns cores 2w, 2w+1
#define CAP     256                    // per-core local bin capacity (mean ~21)
#define MAX_BLK 160

// ------- global scratch (fully overwritten every launch; no resets) ------
__device__ float g_partial[(size_t)MAX_BLK * CD];   // per-block segmax partials
__device__ int   g_pcnt[MAX_BLK * C_CORES];         // per-block per-core counts
__device__ float g_E[CD];                           // final core_embs
__device__ int gb2a, gb2d, gb3a, gb3d;              // self-cleaning barriers

__device__ __forceinline__ float neg_inf() { return __int_as_float(0xff800000); }

#define FMAX4(d, v) { d.x = fmaxf(d.x, (v).x); d.y = fmaxf(d.y, (v).y); \
                      d.z = fmaxf(d.z, (v).z); d.w = fmaxf(d.w, (v).w); }

__global__ __launch_bounds__(TPB, 1)
void fused(const int*   __restrict__ assign,
           const float* __restrict__ emb,
           const float* __restrict__ padding_emb,
           const float* __restrict__ core_con,
           const float* __restrict__ W_self,
           const float* __restrict__ W_msg,
           const float* __restrict__ bvec,
           float*       __restrict__ out,
           int Q)
{
    extern __shared__ char smraw[];
    const int tid  = threadIdx.x;
    const int wid  = tid >> 5;
    const int lane = tid & 31;
    const int grid = gridDim.x;

    const float4* e4 = (const float4*)emb;

    const int chunk = (Q + grid - 1) / grid;
    const int qa0 = blockIdx.x * chunk;
    const int qa1 = min(qa0 + chunk, Q);

    // ============ phase A: bin this block's slice into smem lists =========
    int* s_cnt = (int*)smraw;              // 64
    int* s_bin = s_cnt + C_CORES;          // 64 * CAP
    {
        if (tid < C_CORES) s_cnt[tid] = 0;
        __syncthreads();

        for (int i = qa0 + tid; i < qa1; i += TPB) {
            int c = __ldg(assign + i);
            int idx = atomicAdd(&s_cnt[c], 1);
            if (idx < CAP) s_bin[c * CAP + idx] = i;   // overflow: rescan later
        }
        __syncthreads();

        if (tid < C_CORES)
            g_pcnt[blockIdx.x * C_CORES + tid] = s_cnt[tid];
    }

    // ===== phase B: shfl-clamped register gather-max (R14 body, no atomics)
    {
#pragma unroll
        for (int g = 0; g < 2; g++) {
            const int core  = wid * 2 + g;
            const int ntrue = s_cnt[core];
            const int n     = min(ntrue, CAP);

            float4 acc = make_float4(neg_inf(), neg_inf(), neg_inf(), neg_inf());

            if (n > 0) {
                const int* list = s_bin + core * CAP;
                const int nlast = n - 1;
                const int nb = (n + 7) >> 3;          // 8-row clamped batches

                for (int b = 0; b < nb; b++) {
                    int q32 = list[min(b * 8 + lane, nlast)];
                    float4 v[8];
#pragma unroll
                    for (int u = 0; u < 8; u++) {
                        int q = __shfl_sync(0xffffffffu, q32, u);
                        v[u] = __ldcs(e4 + (size_t)q * 32 + lane);  // LDG.128.CS
                    }
#pragma unroll
                    for (int u = 0; u < 8; u++) FMAX4(acc, v[u]);   // dups: no-op
                }
            }
            if (ntrue > CAP) {
                // never-taken correctness fallback: rescan the whole slice
                for (int i = qa0; i < qa1; i++) {
                    if (__ldg(assign + i) == core) {
                        float4 v = __ldg(e4 + (size_t)i * 32 + lane);
                        FMAX4(acc, v);
                    }
                }
            }
            // plain uncontended write of the partial (always, even if empty)
            float4* gp = (float4*)g_partial + (size_t)blockIdx.x * (CD / 4)
                       + core * 32 + lane;
            *gp = acc;
        }
    }

    // ================= grid barrier (blocks >= 64 exit) ====================
    __threadfence();
    __syncthreads();
    if (blockIdx.x >= C_CORES) {
        if (tid == 0) atomicAdd(&gb2a, 1);
        return;
    }
    if (tid == 0) {
        atomicAdd(&gb2a, 1);
        while (atomicAdd(&gb2a, 0) < grid) __nanosleep(32);
        if (atomicAdd(&gb2d, 1) == C_CORES - 1) {
            atomicExch(&gb2a, 0);
            atomicExch(&gb2d, 0);
        }
        __threadfence();
    }
    __syncthreads();

    // ====== stage 1: block c reduces all partials for core c -> g_E[c] ====
    {
        const int c = blockIdx.x;
        const int t = tid & 127;
        const int s = tid >> 7;                        // 0..7

        float m = neg_inf();
        int cnt = 0;
        for (int p = s; p < grid; p += 8) {
            m = fmaxf(m, __ldcg(&g_partial[(size_t)p * CD + c * D_EMB + t]));
            cnt += __ldcg(&g_pcnt[p * C_CORES + c]);
        }

        float* red  = (float*)smraw;                   // 8 x 128 floats
        int*   redc = (int*)(smraw + 8 * D_EMB * 4);   // 8 ints
        red[s * D_EMB + t] = m;
        if (t == 0) redc[s] = cnt;
        __syncthreads();

        if (s == 0) {
            float mm = red[t];
            int ct = redc[0];
#pragma unroll
            for (int r = 1; r < 8; r++) { mm = fmaxf(mm, red[r * D_EMB + t]); ct += redc[r]; }
            float e = (ct > 0) ? mm : __ldg(&padding_emb[t]);
            g_E[c * D_EMB + t] = e;
        }
    }

    // ---- barrier among the 64 epilogue blocks (g_E complete) --------------
    __threadfence();
    __syncthreads();
    if (tid == 0) {
        atomicAdd(&gb3a, 1);
        while (atomicAdd(&gb3a, 0) < C_CORES) __nanosleep(32);
        if (atomicAdd(&gb3d, 1) == C_CORES - 1) {
            atomicExch(&gb3a, 0);
            atomicExch(&gb3d, 0);
        }
        __threadfence();
    }
    __syncthreads();

    // ====== stage 2: fused GNN epilogue ====================================
    float (*sE)[D_EMB] = (float(*)[D_EMB])smraw;       // 32 KB (reuse)
    float* sMp = (float*)smraw + CD;                   // 8 x 128
    float* sM  = sMp + 8 * D_EMB;                      // 128
    float* sO  = sM + D_EMB;                           // 8 x 128

    const int c = blockIdx.x;
    const int t = tid & 127;
    const int s = tid >> 7;                            // 0..7

#pragma unroll
    for (int j = s * 8; j < s * 8 + 8; j++)
        sE[j][t] = __ldcg(&g_E[j * D_EMB + t]);
    __syncthreads();

    // Msum[t] = sum_j con[c,j] * E[j,t]   (8-way split)
    {
        float a = 0.f;
#pragma unroll
        for (int j = s * 8; j < s * 8 + 8; j++)
            a = fmaf(__ldg(&core_con[c * C_CORES + j]), sE[j][t], a);
        sMp[s * D_EMB + t] = a;
    }
    __syncthreads();
    if (s == 0) {
        float m = 0.f;
#pragma unroll
        for (int r = 0; r < 8; r++) m += sMp[r * D_EMB + t];
        sM[t] = m;
    }
    __syncthreads();

    // out = relu(E@W_self + Msum@W_msg + b)   (8-way K split)
    {
        float a0 = 0.f, a1 = 0.f;
#pragma unroll
        for (int kk = s * 16; kk < s * 16 + 16; kk++) {
            a0 = fmaf(sE[c][kk], __ldg(&W_self[kk * D_EMB + t]), a0);
            a1 = fmaf(sM[kk],    __ldg(&W_msg [kk * D_EMB + t]), a1);
        }
        sO[s * D_EMB + t] = a0 + a1;
    }
    __syncthreads();
    if (s == 0) {
        float r = __ldg(&bvec[t]);
#pragma unroll
        for (int q = 0; q < 8; q++) r += sO[q * D_EMB + t];
        out[c * D_EMB + t] = fmaxf(r, 0.f);
    }
}

// ---------------- launch ----------------
extern "C" void kernel_launch(void* const* d_in, const int* in_sizes, int n_in,
                              void* d_out, int out_size)
{
    const int*   assign      = (const int*)  d_in[0];
    const float* emb         = (const float*)d_in[1];
    const float* padding_emb = (const float*)d_in[2];
    const float* core_con    = (const float*)d_in[3];
    const float* W_self      = (const float*)d_in[4];
    const float* W_msg       = (const float*)d_in[5];
    const float* bvec        = (const float*)d_in[6];
    float* out = (float*)d_out;

    const int Q = in_sizes[0];

    int nsm = 148;
    cudaDeviceGetAttribute(&nsm, cudaDevAttrMultiProcessorCount, 0);
    if (nsm < C_CORES) nsm = C_CORES;
    if (nsm > MAX_BLK) nsm = MAX_BLK;

    // smem: max(phase A bins: (64 + 64*256)*4 = 65.8 KB, epilogue: 41.5 KB)
    int smem1 = (C_CORES + C_CORES * CAP) * (int)sizeof(int);
    int smem2 = (CD + 17 * D_EMB) * (int)sizeof(float);
    int smem  = (smem1 > smem2 ? smem1 : smem2);

    cudaFuncSetAttribute(fused, cudaFuncAttributeMaxDynamicSharedMemorySize, smem);
    fused<<<nsm, TPB, smem>>>(assign, emb, padding_emb, core_con,
                              W_self, W_msg, bvec, out, Q);
}